// round 7
// baseline (speedup 1.0000x reference)
#include <cuda_runtime.h>
#include <cuda_bf16.h>
#include <stdint.h>

#define MAXN   102400
#define MAXE   1050000
#define DIMF   128
#define MAXG   1024
#define SCAN_B 1024
#define MAXNB  (MAXN / SCAN_B)   // 100

// ---------------- scratch (static device memory; no allocations) -------------
__device__ __align__(16) float g_h[(size_t)MAXN * DIMF];   // layer-1 output
__device__ float g_dis[MAXN];
__device__ int   g_deg[MAXN];
__device__ int   g_rowptr[MAXN];
__device__ int   g_cur[MAXN];
__device__ int   g_bsum[MAXNB + 1];
__device__ __align__(16) int2 g_csr[MAXE];
__device__ float g_gsum[MAXG];
__device__ int   g_gcnt[MAXG];
__device__ int   g_roles[3];   // [0]=bias-l1, [1]=bias-l2, [2]=Wfc (index into c0..c2)
__device__ int   g_is64[2];    // [0]=edge_index is int64, [1]=batch is int64

// ---------------- helpers ------------------------------------------------------
__device__ __forceinline__ const float* pick3(const float* c0, const float* c1,
                                              const float* c2, int i) {
    return i == 0 ? c0 : (i == 1 ? c1 : c2);
}

__device__ __forceinline__ int load_idx(const void* p, long long i, int is64) {
    return is64 ? (int)((const long long*)p)[i] : ((const int*)p)[i];
}

// ---------------- dtype probe + role selection --------------------------------
__global__ void k_detect(const void* ei, int E, const void* batch, int N,
                         const float* __restrict__ c0, const float* __restrict__ c1,
                         const float* __restrict__ c2) {
    if (threadIdx.x != 0 || blockIdx.x != 0) return;

    const int* w = (const int*)ei;
    int all0 = 1;
    for (int t = 0; t < 64; ++t) {
        long long k = ((long long)t * (E - 1)) / 63;
        if (w[2 * k + 1] != 0) { all0 = 0; break; }
    }
    g_is64[0] = all0;

    const int* bw = (const int*)batch;
    int base = N / 4;
    if (base + 64 > (N - 1) / 2) base = 0;
    all0 = 1;
    for (int t = 0; t < 64; ++t) {
        if (bw[2 * (base + t) + 1] != 0) { all0 = 0; break; }
    }
    g_is64[1] = all0;

    float s0 = 0.f, s1 = 0.f, s2 = 0.f;
    for (int i = 0; i < DIMF; ++i) {
        s0 += fabsf(c0[i]); s1 += fabsf(c1[i]); s2 += fabsf(c2[i]);
    }
    int nz = (s0 > 0.f) + (s1 > 0.f) + (s2 > 0.f);
    int wfc = 2;  // positional fallback (insertion order: b1, b2, Wfc)
    if (nz == 1) wfc = (s0 > 0.f) ? 0 : ((s1 > 0.f) ? 1 : 2);
    int b = 0;
    for (int i = 0; i < 3; ++i) if (i != wfc) g_roles[b++] = i;
    g_roles[2] = wfc;
}

// ---------------- degree / normalization / graph counts -----------------------
__global__ void k_zero(int n, int G) {
    int i = blockIdx.x * blockDim.x + threadIdx.x;
    if (i < n) g_deg[i] = 0;
    if (i < G) { g_gsum[i] = 0.f; g_gcnt[i] = 0; }
}

__global__ void k_hist(const void* __restrict__ ei, int E, int n) {
    int e = blockIdx.x * blockDim.x + threadIdx.x;
    if (e < E) {
        int d = load_idx(ei, (long long)E + e, g_is64[0]);
        d = min(max(d, 0), n - 1);
        atomicAdd(&g_deg[d], 1);
    }
}

__global__ void k_dis_cnt(const void* __restrict__ batch, int n, int G) {
    int i = blockIdx.x * blockDim.x + threadIdx.x;
    if (i < n) {
        g_dis[i] = rsqrtf((float)g_deg[i] + 1.0f);  // +1 self loop
        int g = load_idx(batch, i, g_is64[1]);
        g = min(max(g, 0), G - 1);
        atomicAdd(&g_gcnt[g], 1);
    }
}

// ---------------- exclusive prefix scan of g_deg -> g_rowptr ------------------
__global__ void k_scan1(int n) {
    __shared__ int s[SCAN_B];
    int i = blockIdx.x * SCAN_B + threadIdx.x;
    int v = (i < n) ? g_deg[i] : 0;
    s[threadIdx.x] = v;
    __syncthreads();
#pragma unroll
    for (int off = 1; off < SCAN_B; off <<= 1) {
        int t = (threadIdx.x >= off) ? s[threadIdx.x - off] : 0;
        __syncthreads();
        s[threadIdx.x] += t;
        __syncthreads();
    }
    if (i < n) g_rowptr[i] = s[threadIdx.x] - v;
    if (threadIdx.x == SCAN_B - 1) g_bsum[blockIdx.x] = s[SCAN_B - 1];
}

__global__ void k_scan2(int nb) {  // single block of 128 threads
    __shared__ int s[MAXNB];
    int v = 0;
    if (threadIdx.x < MAXNB) {
        v = (threadIdx.x < nb) ? g_bsum[threadIdx.x] : 0;
        s[threadIdx.x] = v;
    }
    __syncthreads();
    for (int off = 1; off < MAXNB; off <<= 1) {
        int t = (threadIdx.x >= off && threadIdx.x < MAXNB) ? s[threadIdx.x - off] : 0;
        __syncthreads();
        if (threadIdx.x < MAXNB) s[threadIdx.x] += t;
        __syncthreads();
    }
    if (threadIdx.x < nb) g_bsum[threadIdx.x] = s[threadIdx.x] - v;
}

__global__ void k_scan3(int n) {
    int i = blockIdx.x * blockDim.x + threadIdx.x;
    if (i < n) {
        g_rowptr[i] += g_bsum[i / SCAN_B];
        g_cur[i] = 0;
    }
}

// ---------------- CSR fill -----------------------------------------------------
__global__ void k_fill(const void* __restrict__ ei, int E, int n) {
    int e = blockIdx.x * blockDim.x + threadIdx.x;
    if (e >= E) return;
    int is64 = g_is64[0];
    int s = load_idx(ei, e, is64);
    int d = load_idx(ei, (long long)E + e, is64);
    s = min(max(s, 0), n - 1);
    d = min(max(d, 0), n - 1);
    int pos = atomicAdd(&g_cur[d], 1);
    int slot = g_rowptr[d] + pos;
    if (slot >= MAXE) return;
    float nrm = g_dis[s] * g_dis[d];
    g_csr[slot] = make_int2(s, __float_as_int(nrm));
}

// ---------------- fused layer: out = relu(agg(in) @ W + b)  [+ optional pool] --
// Phase 1: warp w aggregates rows w*8..w*8+7 of agg(in) into smem (CSR gather).
// Phase 2: 64x128 @ 128x128 GEMM on the smem tile (packed f32x2, 8x4 per thread).
// Epilogue: +bias, relu; either store row (layer 1) or dot with Wfc and pool
// into per-graph accumulators (layer 2 — no global feature write at all).
template <bool EXT, bool POOL>
__global__ void k_fused(const float* __restrict__ Xext, const float* __restrict__ Wm,
                        const float* __restrict__ c0, const float* __restrict__ c1,
                        const float* __restrict__ c2, int layer,
                        const void* __restrict__ batch, int n, int G) {
    const float* __restrict__ X = EXT ? Xext : (const float*)g_h;
    __shared__ float xs[64][DIMF];
    const int tid  = threadIdx.x;
    const int lane = tid & 31;
    const int wrp  = tid >> 5;   // 0..7
    const int cg   = tid & 31;
    const int rg   = tid >> 5;
    const int row0 = blockIdx.x * 64;

    // ---- phase 1: gather-aggregate 8 rows per warp into smem ----
#pragma unroll
    for (int i = 0; i < 8; ++i) {
        int r = wrp * 8 + i;
        int rr = row0 + r;
        float4 acc = make_float4(0.f, 0.f, 0.f, 0.f);
        if (rr < n) {
            float ds = g_dis[rr];
            float self = ds * ds;
            acc = __ldg((const float4*)(X + (size_t)rr * DIMF) + lane);
            acc.x *= self; acc.y *= self; acc.z *= self; acc.w *= self;

            int start = g_rowptr[rr];
            int cnt   = g_deg[rr];
            int k = 0;
            for (; k + 2 <= cnt; k += 2) {       // 2-way unroll for MLP
                int2 e0 = __ldg(&g_csr[start + k]);
                int2 e1 = __ldg(&g_csr[start + k + 1]);
                float4 v0 = __ldg((const float4*)(X + (size_t)e0.x * DIMF) + lane);
                float4 v1 = __ldg((const float4*)(X + (size_t)e1.x * DIMF) + lane);
                float n0 = __int_as_float(e0.y);
                float n1 = __int_as_float(e1.y);
                acc.x = fmaf(v0.x, n0, acc.x); acc.y = fmaf(v0.y, n0, acc.y);
                acc.z = fmaf(v0.z, n0, acc.z); acc.w = fmaf(v0.w, n0, acc.w);
                acc.x = fmaf(v1.x, n1, acc.x); acc.y = fmaf(v1.y, n1, acc.y);
                acc.z = fmaf(v1.z, n1, acc.z); acc.w = fmaf(v1.w, n1, acc.w);
            }
            if (k < cnt) {
                int2 e0 = __ldg(&g_csr[start + k]);
                float4 v0 = __ldg((const float4*)(X + (size_t)e0.x * DIMF) + lane);
                float n0 = __int_as_float(e0.y);
                acc.x = fmaf(v0.x, n0, acc.x); acc.y = fmaf(v0.y, n0, acc.y);
                acc.z = fmaf(v0.z, n0, acc.z); acc.w = fmaf(v0.w, n0, acc.w);
            }
        }
        *(float4*)&xs[r][lane * 4] = acc;
    }
    __syncthreads();

    // ---- phase 2: GEMM on smem tile ----
    unsigned long long acc0[8], acc1[8];
#pragma unroll
    for (int r = 0; r < 8; ++r) { acc0[r] = 0ull; acc1[r] = 0ull; }

    const float* wcol = Wm + cg * 4;
#pragma unroll 4
    for (int k = 0; k < DIMF; ++k) {
        double2 wd = *(const double2*)(wcol + (size_t)k * DIMF);
        unsigned long long w01 = __double_as_longlong(wd.x);
        unsigned long long w23 = __double_as_longlong(wd.y);
#pragma unroll
        for (int r = 0; r < 8; ++r) {
            float xv = xs[rg * 8 + r][k];
            unsigned long long x2;
            asm("mov.b64 %0, {%1, %1};" : "=l"(x2) : "f"(xv));
            asm("fma.rn.f32x2 %0, %1, %2, %0;" : "+l"(acc0[r]) : "l"(x2), "l"(w01));
            asm("fma.rn.f32x2 %0, %1, %2, %0;" : "+l"(acc1[r]) : "l"(x2), "l"(w23));
        }
    }

    // ---- epilogue ----
    const float* b = pick3(c0, c1, c2, g_roles[layer]);
    float4 bv = __ldg((const float4*)b + cg);
    float4 wf;
    if (POOL) wf = __ldg((const float4*)pick3(c0, c1, c2, g_roles[2]) + cg);

#pragma unroll
    for (int r = 0; r < 8; ++r) {
        int rr = row0 + rg * 8 + r;
        if (rr >= n) continue;
        float2 a = *(float2*)&acc0[r];
        float2 bb = *(float2*)&acc1[r];
        float4 o = make_float4(fmaxf(a.x + bv.x, 0.f), fmaxf(a.y + bv.y, 0.f),
                               fmaxf(bb.x + bv.z, 0.f), fmaxf(bb.y + bv.w, 0.f));
        if (!POOL) {
            *(float4*)(g_h + (size_t)rr * DIMF + cg * 4) = o;
        } else {
            float s = o.x * wf.x + o.y * wf.y + o.z * wf.z + o.w * wf.w;
#pragma unroll
            for (int off = 16; off; off >>= 1) s += __shfl_xor_sync(0xFFFFFFFFu, s, off);
            if (lane == 0) {
                int g = load_idx(batch, rr, g_is64[1]);
                g = min(max(g, 0), G - 1);
                atomicAdd(&g_gsum[g], s);
            }
        }
    }
}

// ---------------- final --------------------------------------------------------
__global__ void k_final(const float* __restrict__ bfc, float* __restrict__ out, int G) {
    int g = blockIdx.x * blockDim.x + threadIdx.x;
    if (g < G) out[g] = g_gsum[g] / fmaxf((float)g_gcnt[g], 1.0f) + bfc[0];
}

// ---------------- launch -------------------------------------------------------
extern "C" void kernel_launch(void* const* d_in, const int* in_sizes, int n_in,
                              void* d_out, int out_size) {
    // ---- permutation-proof input classification (sizes only) ----
    int ix = 0;
    for (int i = 1; i < n_in; ++i) if (in_sizes[i] > in_sizes[ix]) ix = i;
    const int N = in_sizes[ix] / DIMF;

    int ie = -1;  // second largest = edge_index
    for (int i = 0; i < n_in; ++i) {
        if (i == ix) continue;
        if (ie < 0 || in_sizes[i] > in_sizes[ie]) ie = i;
    }
    int ib = -1;  // size == N -> batch
    for (int i = 0; i < n_in; ++i)
        if (i != ix && i != ie && in_sizes[i] == N) { ib = i; break; }

    int iw[2] = {-1, -1}, nw = 0;
    int ic[3] = {-1, -1, -1}, nc = 0;
    int ibfc = -1;
    for (int i = 0; i < n_in; ++i) {
        if (i == ix || i == ie || i == ib) continue;
        if (in_sizes[i] == DIMF * DIMF && nw < 2) iw[nw++] = i;
        else if (in_sizes[i] == DIMF && nc < 3) ic[nc++] = i;
        else if (in_sizes[i] == 1 && ibfc < 0) ibfc = i;
    }

    const float* x     = (const float*)d_in[ix];
    const void*  ei    = d_in[ie];
    const void*  batch = d_in[ib];
    const float* W1    = (const float*)d_in[iw[0]];
    const float* W2    = (const float*)d_in[iw[1]];
    const float* c0    = (const float*)d_in[ic[0]];
    const float* c1    = (const float*)d_in[ic[1]];
    const float* c2    = (const float*)d_in[ic[2]];
    const float* bfc   = (const float*)d_in[ibfc];
    float*       out   = (float*)d_out;

    const int E = in_sizes[ie] / 2;
    const int G = out_size;
    const int NB = (N + SCAN_B - 1) / SCAN_B;

    const int B = 256;
    dim3 gN((N + B - 1) / B);
    dim3 gE((E + B - 1) / B);
    dim3 gFused((N + 63) / 64);

    // probe + preproc (CSR by destination)
    k_detect<<<1, 32>>>(ei, E, batch, N, c0, c1, c2);
    k_zero<<<gN, B>>>(N, G);
    k_hist<<<gE, B>>>(ei, E, N);
    k_dis_cnt<<<gN, B>>>(batch, N, G);
    k_scan1<<<NB, SCAN_B>>>(N);
    k_scan2<<<1, 128>>>(NB);
    k_scan3<<<gN, B>>>(N);
    k_fill<<<gE, B>>>(ei, E, N);

    // layer 1: h1 = relu(agg(x) @ W1 + b1)
    k_fused<true,  false><<<gFused, B>>>(x, W1, c0, c1, c2, 0, batch, N, G);
    // layer 2 + pooling: gsum[g] += relu(agg(h1) @ W2 + b2) . Wfc
    k_fused<false, true ><<<gFused, B>>>(nullptr, W2, c0, c1, c2, 1, batch, N, G);

    // final: mean + bias
    k_final<<<(G + B - 1) / B, B>>>(bfc, out, G);
}

// round 8
// speedup vs baseline: 1.1638x; 1.1638x over previous
#include <cuda_runtime.h>
#include <cuda_bf16.h>
#include <stdint.h>

#define MAXN   102400
#define MAXE   1050000
#define DIMF   128
#define MAXG   1024
#define SCAN_B 1024
#define MAXNB  (MAXN / SCAN_B)   // 100

// ---------------- scratch (static device memory; no allocations) -------------
__device__ __align__(16) float g_h[(size_t)MAXN * DIMF];    // GEMM outputs
__device__ __align__(16) float g_agg[(size_t)MAXN * DIMF];  // layer-1 activations
__device__ float g_dis[MAXN];
__device__ int   g_deg[MAXN];
__device__ int   g_rowptr[MAXN];
__device__ int   g_cur[MAXN];
__device__ int   g_bsum[MAXNB + 1];
__device__ __align__(16) int2 g_csr[MAXE];
__device__ float g_gsum[MAXG];
__device__ int   g_gcnt[MAXG];
__device__ int   g_roles[3];   // [0]=bias-l1, [1]=bias-l2, [2]=Wfc (index into c0..c2)
__device__ int   g_is64[2];    // [0]=edge_index is int64, [1]=batch is int64

// ---------------- helpers ------------------------------------------------------
__device__ __forceinline__ const float* pick3(const float* c0, const float* c1,
                                              const float* c2, int i) {
    return i == 0 ? c0 : (i == 1 ? c1 : c2);
}

__device__ __forceinline__ int load_idx(const void* p, long long i, int is64) {
    return is64 ? (int)((const long long*)p)[i] : ((const int*)p)[i];
}

// ---------------- dtype probe + role selection --------------------------------
__global__ void k_detect(const void* ei, int E, const void* batch, int N,
                         const float* __restrict__ c0, const float* __restrict__ c1,
                         const float* __restrict__ c2) {
    if (threadIdx.x != 0 || blockIdx.x != 0) return;

    const int* w = (const int*)ei;
    int all0 = 1;
    for (int t = 0; t < 64; ++t) {
        long long k = ((long long)t * (E - 1)) / 63;
        if (w[2 * k + 1] != 0) { all0 = 0; break; }
    }
    g_is64[0] = all0;

    const int* bw = (const int*)batch;
    int base = N / 4;
    if (base + 64 > (N - 1) / 2) base = 0;
    all0 = 1;
    for (int t = 0; t < 64; ++t) {
        if (bw[2 * (base + t) + 1] != 0) { all0 = 0; break; }
    }
    g_is64[1] = all0;

    float s0 = 0.f, s1 = 0.f, s2 = 0.f;
    for (int i = 0; i < DIMF; ++i) {
        s0 += fabsf(c0[i]); s1 += fabsf(c1[i]); s2 += fabsf(c2[i]);
    }
    int nz = (s0 > 0.f) + (s1 > 0.f) + (s2 > 0.f);
    int wfc = 2;  // positional fallback (insertion order: b1, b2, Wfc)
    if (nz == 1) wfc = (s0 > 0.f) ? 0 : ((s1 > 0.f) ? 1 : 2);
    int b = 0;
    for (int i = 0; i < 3; ++i) if (i != wfc) g_roles[b++] = i;
    g_roles[2] = wfc;
}

// ---------------- degree / normalization / graph counts -----------------------
__global__ void k_zero(int n, int G) {
    int i = blockIdx.x * blockDim.x + threadIdx.x;
    if (i < n) g_deg[i] = 0;
    if (i < G) g_gsum[i] = 0.f;
}

__global__ void k_hist(const void* __restrict__ ei, int E, int n) {
    int e = blockIdx.x * blockDim.x + threadIdx.x;
    if (e < E) {
        int d = load_idx(ei, (long long)E + e, g_is64[0]);
        d = min(max(d, 0), n - 1);
        atomicAdd(&g_deg[d], 1);
    }
}

__global__ void k_dis(int n) {
    int i = blockIdx.x * blockDim.x + threadIdx.x;
    if (i < n) g_dis[i] = rsqrtf((float)g_deg[i] + 1.0f);  // +1 self loop
}

// counts per graph via binary search on sorted batch — no atomics
__global__ void k_counts(const void* __restrict__ batch, int n, int G) {
    int g = blockIdx.x * blockDim.x + threadIdx.x;
    if (g >= G) return;
    int is64 = g_is64[1];
    // lower_bound(g) and lower_bound(g+1)
    int lo = 0, hi = n;
    while (lo < hi) { int m = (lo + hi) >> 1; if (load_idx(batch, m, is64) < g) lo = m + 1; else hi = m; }
    int lb = lo;
    hi = n;
    while (lo < hi) { int m = (lo + hi) >> 1; if (load_idx(batch, m, is64) < g + 1) lo = m + 1; else hi = m; }
    g_gcnt[g] = lo - lb;
}

// ---------------- exclusive prefix scan of g_deg -> g_rowptr ------------------
__global__ void k_scan1(int n) {
    __shared__ int s[SCAN_B];
    int i = blockIdx.x * SCAN_B + threadIdx.x;
    int v = (i < n) ? g_deg[i] : 0;
    s[threadIdx.x] = v;
    __syncthreads();
#pragma unroll
    for (int off = 1; off < SCAN_B; off <<= 1) {
        int t = (threadIdx.x >= off) ? s[threadIdx.x - off] : 0;
        __syncthreads();
        s[threadIdx.x] += t;
        __syncthreads();
    }
    if (i < n) g_rowptr[i] = s[threadIdx.x] - v;
    if (threadIdx.x == SCAN_B - 1) g_bsum[blockIdx.x] = s[SCAN_B - 1];
}

__global__ void k_scan2(int nb) {  // single block of 128 threads
    __shared__ int s[MAXNB];
    int v = 0;
    if (threadIdx.x < MAXNB) {
        v = (threadIdx.x < nb) ? g_bsum[threadIdx.x] : 0;
        s[threadIdx.x] = v;
    }
    __syncthreads();
    for (int off = 1; off < MAXNB; off <<= 1) {
        int t = (threadIdx.x >= off && threadIdx.x < MAXNB) ? s[threadIdx.x - off] : 0;
        __syncthreads();
        if (threadIdx.x < MAXNB) s[threadIdx.x] += t;
        __syncthreads();
    }
    if (threadIdx.x < nb) g_bsum[threadIdx.x] = s[threadIdx.x] - v;
}

__global__ void k_scan3(int n) {
    int i = blockIdx.x * blockDim.x + threadIdx.x;
    if (i < n) {
        g_rowptr[i] += g_bsum[i / SCAN_B];
        g_cur[i] = 0;
    }
}

// ---------------- CSR fill -----------------------------------------------------
__global__ void k_fill(const void* __restrict__ ei, int E, int n) {
    int e = blockIdx.x * blockDim.x + threadIdx.x;
    if (e >= E) return;
    int is64 = g_is64[0];
    int s = load_idx(ei, e, is64);
    int d = load_idx(ei, (long long)E + e, is64);
    s = min(max(s, 0), n - 1);
    d = min(max(d, 0), n - 1);
    int pos = atomicAdd(&g_cur[d], 1);
    int slot = g_rowptr[d] + pos;
    if (slot >= MAXE) return;
    float nrm = g_dis[s] * g_dis[d];
    g_csr[slot] = make_int2(s, __float_as_int(nrm));
}

// ---------------- GEMM: g_h[n,128] = X[n,128] @ W[128,128] --------------------
// Block tile 64 rows, 256 threads; each thread 8 rows x 4 cols, packed f32x2.
template <bool EXT>
__global__ void k_gemm128(const float* __restrict__ Xext, const float* __restrict__ Wm, int n) {
    const float* __restrict__ X = EXT ? Xext : (const float*)g_agg;
    __shared__ float xs[64][DIMF];
    const int tid = threadIdx.x;
    const int cg = tid & 31;
    const int rg = tid >> 5;
    const int row0 = blockIdx.x * 64;

#pragma unroll
    for (int it = 0; it < 8; ++it) {
        int idx = it * 256 + tid;
        int r = idx >> 5;
        int c = idx & 31;
        float4 v = make_float4(0.f, 0.f, 0.f, 0.f);
        if (row0 + r < n)
            v = *(const float4*)(X + (size_t)(row0 + r) * DIMF + c * 4);
        *(float4*)&xs[r][c * 4] = v;
    }
    __syncthreads();

    unsigned long long acc0[8], acc1[8];
#pragma unroll
    for (int r = 0; r < 8; ++r) { acc0[r] = 0ull; acc1[r] = 0ull; }

    const float* wcol = Wm + cg * 4;
#pragma unroll 4
    for (int k = 0; k < DIMF; ++k) {
        double2 wd = *(const double2*)(wcol + (size_t)k * DIMF);
        unsigned long long w01 = __double_as_longlong(wd.x);
        unsigned long long w23 = __double_as_longlong(wd.y);
#pragma unroll
        for (int r = 0; r < 8; ++r) {
            float xv = xs[rg * 8 + r][k];
            unsigned long long x2;
            asm("mov.b64 %0, {%1, %1};" : "=l"(x2) : "f"(xv));
            asm("fma.rn.f32x2 %0, %1, %2, %0;" : "+l"(acc0[r]) : "l"(x2), "l"(w01));
            asm("fma.rn.f32x2 %0, %1, %2, %0;" : "+l"(acc1[r]) : "l"(x2), "l"(w23));
        }
    }

#pragma unroll
    for (int r = 0; r < 8; ++r) {
        int rr = row0 + rg * 8 + r;
        if (rr < n) {
            float2 a = *(float2*)&acc0[r];
            float2 b = *(float2*)&acc1[r];
            *(float4*)(g_h + (size_t)rr * DIMF + cg * 4) = make_float4(a.x, a.y, b.x, b.y);
        }
    }
}

// ---------------- aggregation: one warp per node, 4-way unrolled gather -------
// acc = sum_{e: dst=i} g_h[src_e]*nrm_e + g_h[i]*dis^2 + bias ; relu.
// POOL=false: store relu(acc) to g_agg.  POOL=true: s = relu(acc).Wfc, warp-
// reduce, one scalar atomic per node into g_gsum[graph].
template <bool POOL>
__global__ void k_aggregate(const float* __restrict__ c0, const float* __restrict__ c1,
                            const float* __restrict__ c2, int layer,
                            const void* __restrict__ batch, int n, int G) {
    int node = (blockIdx.x * blockDim.x + threadIdx.x) >> 5;
    int lane = threadIdx.x & 31;
    if (node >= n) return;

    float self = g_dis[node];
    self *= self;
    float4 acc = __ldg((const float4*)(g_h + (size_t)node * DIMF) + lane);
    acc.x *= self; acc.y *= self; acc.z *= self; acc.w *= self;

    int start = g_rowptr[node];
    int cnt   = g_deg[node];
    int k = 0;
    for (; k + 4 <= cnt; k += 4) {
        int2 e0 = __ldg(&g_csr[start + k]);
        int2 e1 = __ldg(&g_csr[start + k + 1]);
        int2 e2 = __ldg(&g_csr[start + k + 2]);
        int2 e3 = __ldg(&g_csr[start + k + 3]);
        float4 v0 = __ldg((const float4*)(g_h + (size_t)e0.x * DIMF) + lane);
        float4 v1 = __ldg((const float4*)(g_h + (size_t)e1.x * DIMF) + lane);
        float4 v2 = __ldg((const float4*)(g_h + (size_t)e2.x * DIMF) + lane);
        float4 v3 = __ldg((const float4*)(g_h + (size_t)e3.x * DIMF) + lane);
        float n0 = __int_as_float(e0.y), n1 = __int_as_float(e1.y);
        float n2 = __int_as_float(e2.y), n3 = __int_as_float(e3.y);
        acc.x = fmaf(v0.x, n0, acc.x); acc.y = fmaf(v0.y, n0, acc.y);
        acc.z = fmaf(v0.z, n0, acc.z); acc.w = fmaf(v0.w, n0, acc.w);
        acc.x = fmaf(v1.x, n1, acc.x); acc.y = fmaf(v1.y, n1, acc.y);
        acc.z = fmaf(v1.z, n1, acc.z); acc.w = fmaf(v1.w, n1, acc.w);
        acc.x = fmaf(v2.x, n2, acc.x); acc.y = fmaf(v2.y, n2, acc.y);
        acc.z = fmaf(v2.z, n2, acc.z); acc.w = fmaf(v2.w, n2, acc.w);
        acc.x = fmaf(v3.x, n3, acc.x); acc.y = fmaf(v3.y, n3, acc.y);
        acc.z = fmaf(v3.z, n3, acc.z); acc.w = fmaf(v3.w, n3, acc.w);
    }
    for (; k < cnt; ++k) {
        int2 e0 = __ldg(&g_csr[start + k]);
        float nrm = __int_as_float(e0.y);
        float4 v = __ldg((const float4*)(g_h + (size_t)e0.x * DIMF) + lane);
        acc.x = fmaf(v.x, nrm, acc.x); acc.y = fmaf(v.y, nrm, acc.y);
        acc.z = fmaf(v.z, nrm, acc.z); acc.w = fmaf(v.w, nrm, acc.w);
    }

    const float* b = pick3(c0, c1, c2, g_roles[layer]);
    float4 bv = __ldg((const float4*)b + lane);
    acc.x = fmaxf(acc.x + bv.x, 0.f);
    acc.y = fmaxf(acc.y + bv.y, 0.f);
    acc.z = fmaxf(acc.z + bv.z, 0.f);
    acc.w = fmaxf(acc.w + bv.w, 0.f);

    if (!POOL) {
        *((float4*)(g_agg + (size_t)node * DIMF) + lane) = acc;
    } else {
        float4 wf = __ldg((const float4*)pick3(c0, c1, c2, g_roles[2]) + lane);
        float s = acc.x * wf.x + acc.y * wf.y + acc.z * wf.z + acc.w * wf.w;
#pragma unroll
        for (int o = 16; o; o >>= 1) s += __shfl_xor_sync(0xFFFFFFFFu, s, o);
        if (lane == 0) {
            int g = load_idx(batch, node, g_is64[1]);
            g = min(max(g, 0), G - 1);
            atomicAdd(&g_gsum[g], s);
        }
    }
}

// ---------------- final --------------------------------------------------------
__global__ void k_final(const float* __restrict__ bfc, float* __restrict__ out, int G) {
    int g = blockIdx.x * blockDim.x + threadIdx.x;
    if (g < G) out[g] = g_gsum[g] / fmaxf((float)g_gcnt[g], 1.0f) + bfc[0];
}

// ---------------- launch -------------------------------------------------------
extern "C" void kernel_launch(void* const* d_in, const int* in_sizes, int n_in,
                              void* d_out, int out_size) {
    // ---- permutation-proof input classification (sizes only) ----
    int ix = 0;
    for (int i = 1; i < n_in; ++i) if (in_sizes[i] > in_sizes[ix]) ix = i;
    const int N = in_sizes[ix] / DIMF;

    int ie = -1;
    for (int i = 0; i < n_in; ++i) {
        if (i == ix) continue;
        if (ie < 0 || in_sizes[i] > in_sizes[ie]) ie = i;
    }
    int ib = -1;
    for (int i = 0; i < n_in; ++i)
        if (i != ix && i != ie && in_sizes[i] == N) { ib = i; break; }

    int iw[2] = {-1, -1}, nw = 0;
    int ic[3] = {-1, -1, -1}, nc = 0;
    int ibfc = -1;
    for (int i = 0; i < n_in; ++i) {
        if (i == ix || i == ie || i == ib) continue;
        if (in_sizes[i] == DIMF * DIMF && nw < 2) iw[nw++] = i;
        else if (in_sizes[i] == DIMF && nc < 3) ic[nc++] = i;
        else if (in_sizes[i] == 1 && ibfc < 0) ibfc = i;
    }

    const float* x     = (const float*)d_in[ix];
    const void*  ei    = d_in[ie];
    const void*  batch = d_in[ib];
    const float* W1    = (const float*)d_in[iw[0]];
    const float* W2    = (const float*)d_in[iw[1]];
    const float* c0    = (const float*)d_in[ic[0]];
    const float* c1    = (const float*)d_in[ic[1]];
    const float* c2    = (const float*)d_in[ic[2]];
    const float* bfc   = (const float*)d_in[ibfc];
    float*       out   = (float*)d_out;

    const int E = in_sizes[ie] / 2;
    const int G = out_size;
    const int NB = (N + SCAN_B - 1) / SCAN_B;

    const int B = 256;
    dim3 gN((N + B - 1) / B);
    dim3 gE((E + B - 1) / B);
    dim3 gNodeWarp((N * 32 + B - 1) / B);
    dim3 gGemm((N + 63) / 64);

    // probe + preproc
    k_detect<<<1, 32>>>(ei, E, batch, N, c0, c1, c2);
    k_zero<<<gN, B>>>(N, G);
    k_hist<<<gE, B>>>(ei, E, N);
    k_dis<<<gN, B>>>(N);
    k_counts<<<(G + B - 1) / B, B>>>(batch, N, G);
    k_scan1<<<NB, SCAN_B>>>(N);
    k_scan2<<<1, 128>>>(NB);
    k_scan3<<<gN, B>>>(N);
    k_fill<<<gE, B>>>(ei, E, N);

    // layer 1: g_agg = relu(agg(x @ W1) + b1)
    k_gemm128<true><<<gGemm, B>>>(x, W1, N);
    k_aggregate<false><<<gNodeWarp, B>>>(c0, c1, c2, 0, batch, N, G);

    // layer 2 + pool: gsum[g] += relu(agg(g_agg @ W2) + b2) . Wfc
    k_gemm128<false><<<gGemm, B>>>(nullptr, W2, N);
    k_aggregate<true><<<gNodeWarp, B>>>(c0, c1, c2, 1, batch, N, G);

    // final: mean + bias
    k_final<<<(G + B - 1) / B, B>>>(bfc, out, G);
}